// round 9
// baseline (speedup 1.0000x reference)
#include <cuda_runtime.h>
#include <cuda_bf16.h>

// AnisotropicDistance:
// out[b,i,j] = alpha_i * max(||p_i-p_j||^2 + along^2*(||t_i||^2 - 2), 0) + beta_i * along^2
// along = (p_i.t_i) - (p_j.t_i)
//
// R8: single fused kernel (no precompute launch — it cost ~2.5us of serialized
// launch/drain). Per-i constants computed in-block by threads 0..15 into smem;
// j-side points read directly from AoS input as 3 aligned float4s per thread
// and shuffled into packed f32x2 lanes once. Math/store path identical to the
// best-measured R7 config (TI=16, TPB=256, JV=4, f32x2, alpha-folded, __stcs).

typedef unsigned long long ull;

#define FMA2(d, a, b, c) asm("fma.rn.f32x2 %0, %1, %2, %3;" : "=l"(d) : "l"(a), "l"(b), "l"(c))
#define MUL2(d, a, b)    asm("mul.rn.f32x2 %0, %1, %2;"     : "=l"(d) : "l"(a), "l"(b))
#define PACK2(d, lo, hi) asm("mov.b64 %0, {%1, %2};"        : "=l"(d) : "f"(lo), "f"(hi))
#define UNPACK2(lo, hi, s) asm("mov.b64 {%0, %1}, %2;"      : "=f"(lo), "=f"(hi) : "l"(s))

__device__ __forceinline__ ull dup_f(float v) {
    ull d; PACK2(d, v, v); return d;
}

#define TI 16          // i-rows per block
#define TPB 256        // threads per block
#define JV 4           // j per thread (one float4 store) -> block covers 1024 j

// Compute one packed pair (2 j-elements) -> result (max folded via alpha>0)
#define PAIR_COMPUTE(pjx, pjy, pjz, sqj, olo, ohi)                     \
    {                                                                  \
        ull u, a2, s, t2;                                              \
        FMA2(u, pjz, ntz, pds);                                        \
        FMA2(u, pjy, nty, u);                                          \
        FMA2(u, pjx, ntx, u);            /* along */                   \
        MUL2(a2, u, u);                  /* along^2 */                 \
        FMA2(s, pjz, alnpz, alsqi);                                    \
        FMA2(s, pjy, alnpy, s);                                        \
        FMA2(s, pjx, alnpx, s);          /* al*(sqi - 2 pj.pi) */      \
        FMA2(s, a2, alc1, s);            /* + al*c1*a2 */              \
        FMA2(s, al, sqj, s);             /* + al*sqj = al*ns */        \
        MUL2(t2, be, a2);                /* beta*a2 */                 \
        float s0, s1, b0, b1;                                          \
        UNPACK2(s0, s1, s);                                            \
        UNPACK2(b0, b1, t2);                                           \
        olo = fmaxf(s0, 0.0f) + b0;                                    \
        ohi = fmaxf(s1, 0.0f) + b1;                                    \
    }

__global__ __launch_bounds__(TPB, 4) void aniso_fused_kernel(
    const float* __restrict__ points,
    const float* __restrict__ pdir,
    const float* __restrict__ lin,
    float* __restrict__ out, int N) {
    // s_c layout per i: slot0 (ntx,nty) slot1 (ntz,pds) slot2 (alnpx,alnpy)
    //                   slot3 (alnpz,alc1) slot4 (al,be) slot5 (alsqi,alsqi)
    __shared__ ulonglong2 s_c[TI * 6];

    const int b  = blockIdx.z;
    const int i0 = blockIdx.y * TI;
    const int j4 = blockIdx.x * TPB + threadIdx.x;   // float4 index in j
    const int base = b * N;

    // ---- i-side constants: threads 0..15 compute from raw inputs ----
    if (threadIdx.x < TI) {
        const int gi = base + i0 + threadIdx.x;
        const float px = points[gi * 3 + 0];
        const float py = points[gi * 3 + 1];
        const float pz = points[gi * 3 + 2];
        const float tx = pdir[gi * 3 + 0];
        const float ty = pdir[gi * 3 + 1];
        const float tz = pdir[gi * 3 + 2];
        const float l  = lin[gi];

        const float sq = fmaf(px, px, fmaf(py, py, pz * pz));
        const float al = 2.0f * (1.0f + l);
        const float be = 0.5f * (1.0f - l);
        const float c1 = fmaf(tx, tx, fmaf(ty, ty, tz * tz)) - 2.0f;

        ulonglong2 c;
        c.x = dup_f(-tx);             c.y = dup_f(-ty);
        s_c[threadIdx.x * 6 + 0] = c;
        c.x = dup_f(-tz);             c.y = dup_f(fmaf(px, tx, fmaf(py, ty, pz * tz)));
        s_c[threadIdx.x * 6 + 1] = c;
        c.x = dup_f(al * -2.0f * px); c.y = dup_f(al * -2.0f * py);
        s_c[threadIdx.x * 6 + 2] = c;
        c.x = dup_f(al * -2.0f * pz); c.y = dup_f(al * c1);
        s_c[threadIdx.x * 6 + 3] = c;
        c.x = dup_f(al);              c.y = dup_f(be);
        s_c[threadIdx.x * 6 + 4] = c;
        c.x = dup_f(al * sq);         c.y = dup_f(al * sq);
        s_c[threadIdx.x * 6 + 5] = c;
    }
    __syncthreads();

    // ---- j-side: 4 points = 12 contiguous floats = 3 aligned float4 loads ----
    // float index of first coord: (base + j4*4)*3 = base*3 + j4*12.
    // base*3 = b*N*3 is divisible by 4 (N=8192), so float4 indexing is exact.
    const float4* p4 = reinterpret_cast<const float4*>(points);
    const int f4base = (base * 3) >> 2;
    const float4 q0 = p4[f4base + j4 * 3 + 0];   // px0 py0 pz0 px1
    const float4 q1 = p4[f4base + j4 * 3 + 1];   // py1 pz1 px2 py2
    const float4 q2 = p4[f4base + j4 * 3 + 2];   // pz2 px3 py3 pz3

    ull ax01, ax23, ay01, ay23, az01, az23;
    PACK2(ax01, q0.x, q0.w); PACK2(ay01, q0.y, q1.x); PACK2(az01, q0.z, q1.y);
    PACK2(ax23, q1.z, q2.y); PACK2(ay23, q1.w, q2.z); PACK2(az23, q2.x, q2.w);

    // sqj computed in-registers (loop-invariant), packed f32x2
    ull as01, as23;
    {
        ull t;
        MUL2(t, az01, az01); FMA2(t, ay01, ay01, t); FMA2(as01, ax01, ax01, t);
        MUL2(t, az23, az23); FMA2(t, ay23, ay23, t); FMA2(as23, ax23, ax23, t);
    }

    float* orow = out + ((size_t)b * N + i0) * N + j4 * JV;

    #pragma unroll
    for (int ii = 0; ii < TI; ii++) {
        const ulonglong2 c0 = s_c[ii * 6 + 0];
        const ulonglong2 c1v = s_c[ii * 6 + 1];
        const ulonglong2 c2 = s_c[ii * 6 + 2];
        const ulonglong2 c3 = s_c[ii * 6 + 3];
        const ulonglong2 c4 = s_c[ii * 6 + 4];
        const ulonglong2 c5 = s_c[ii * 6 + 5];
        const ull ntx = c0.x, nty = c0.y, ntz = c1v.x, pds = c1v.y;
        const ull alnpx = c2.x, alnpy = c2.y, alnpz = c3.x, alc1 = c3.y;
        const ull al = c4.x, be = c4.y, alsqi = c5.x;

        float4 o;
        PAIR_COMPUTE(ax01, ay01, az01, as01, o.x, o.y);
        PAIR_COMPUTE(ax23, ay23, az23, as23, o.z, o.w);

        __stcs(reinterpret_cast<float4*>(orow), o);
        orow += N;
    }
}

extern "C" void kernel_launch(void* const* d_in, const int* in_sizes, int n_in,
                              void* d_out, int out_size) {
    const float* points = (const float*)d_in[0];
    const float* pdir   = (const float*)d_in[1];
    const float* lin    = (const float*)d_in[2];
    float* out = (float*)d_out;

    const int total = in_sizes[0] / 3;                 // B*N points
    const int N = (int)((long long)out_size / total);  // out = B*N*N
    const int B = total / N;

    dim3 grid((N + TPB * JV - 1) / (TPB * JV), (N + TI - 1) / TI, B);
    aniso_fused_kernel<<<grid, TPB>>>(points, pdir, lin, out, N);
}